// round 16
// baseline (speedup 1.0000x reference)
#include <cuda_runtime.h>
#include <cuda_fp16.h>
#include <math.h>
#include <stdint.h>

// Problem constants
#define N_TOK 4096
#define D_DIM 1024
#define E_NUM 8
#define H_DIM 2048
#define O_DIM 1024
#define TOPK  2
#define NK    (N_TOK*TOPK)
#define LN_EPS 1e-5f
#define LOSS_COEF 0.01f

// GEMM tiling: 128x128 CTA tile, 4 warps (64x64 warp tile), K slab = 32 halves
#define CTA_M 128
#define CTA_N 128
#define KS    32
#define ROWB  80                        // 64B data + 16B pad (conflict-free LDSM)
#define STAGE_B (256 * ROWB)            // A rows 0..127, B rows 128..255 (20480 B)
#define NTHR  128

// ---------------- scratch (allocation-free; device-side access ONLY) ----------------
__device__ __half g_xnh[(size_t)N_TOK * D_DIM];   // LN output fp16 (gemm1 A via rowtok)
__device__ __half g_xr [(size_t)N_TOK * D_DIM];   // half(x): proj A
__device__ __half g_h  [(size_t)NK   * H_DIM];
__device__ __half g_ehw[(size_t)E_NUM * H_DIM * D_DIM];
__device__ __half g_ew [(size_t)E_NUM * O_DIM * H_DIM];
__device__ __half g_owT[(size_t)O_DIM * D_DIM];
__device__ float g_gates[NK];
__device__ int   g_topidx[NK];
__device__ float g_importance[E_NUM];
__device__ int   g_load[E_NUM];
__device__ int   g_offsets[E_NUM + 1];
__device__ int   g_rowtok[NK];
__device__ float g_rowgate[NK];

// ---------------- helpers ----------------
__device__ __forceinline__ uint32_t smem_u32(const void* p) {
    uint32_t a;
    asm("{ .reg .u64 t; cvta.to.shared.u64 t, %1; cvt.u32.u64 %0, t; }" : "=r"(a) : "l"(p));
    return a;
}
__device__ __forceinline__ void cpasync16(uint32_t dst, const void* src) {
    asm volatile("cp.async.cg.shared.global [%0], [%1], 16;\n" :: "r"(dst), "l"(src));
}
#define CP_COMMIT() asm volatile("cp.async.commit_group;\n")
#define CP_WAIT(N)  asm volatile("cp.async.wait_group %0;\n" :: "n"(N))

__device__ __forceinline__ void ldsm4(uint32_t* r, uint32_t addr) {
    asm volatile("ldmatrix.sync.aligned.m8n8.x4.shared.b16 {%0,%1,%2,%3}, [%4];"
        : "=r"(r[0]), "=r"(r[1]), "=r"(r[2]), "=r"(r[3]) : "r"(addr));
}
__device__ __forceinline__ void mma16(float* c, const uint32_t* a, const uint32_t* b) {
    asm volatile("mma.sync.aligned.m16n8k16.row.col.f32.f16.f16.f32 "
        "{%0,%1,%2,%3}, {%4,%5,%6,%7}, {%8,%9}, {%0,%1,%2,%3};"
        : "+f"(c[0]), "+f"(c[1]), "+f"(c[2]), "+f"(c[3])
        : "r"(a[0]), "r"(a[1]), "r"(a[2]), "r"(a[3]), "r"(b[0]), "r"(b[1]));
}
__inline__ __device__ float warpRed(float v) {
    #pragma unroll
    for (int o = 16; o; o >>= 1) v += __shfl_xor_sync(0xffffffffu, v, o);
    return v;
}

// ================= prep: init + transpose_ow + cvt(ehw), one launch =================
#define PREP_T  1024
#define CVT_CNT (E_NUM * H_DIM * D_DIM / 8)    // 2097152 groups of 8
__global__ void prep_kernel(const float* __restrict__ ow,
                            const float* __restrict__ ehw) {
    int bid = blockIdx.x;
    int t = threadIdx.x;
    if (bid == 0 && t < E_NUM) { g_importance[t] = 0.f; g_load[t] = 0; }
    if (bid < PREP_T) {
        __shared__ float tile[32][33];
        int ox = bid & 31, dy = bid >> 5;
        int tx = t & 31, ty = t >> 5;
        int o = ox * 32 + tx;
        int d0 = dy * 32;
        #pragma unroll
        for (int j = 0; j < 4; j++)
            tile[ty + j * 8][tx] = ow[(size_t)(d0 + ty + j * 8) * O_DIM + o];
        __syncthreads();
        int d = d0 + tx;
        int o2 = ox * 32;
        #pragma unroll
        for (int j = 0; j < 4; j++)
            g_owT[(size_t)(o2 + ty + j * 8) * D_DIM + d] =
                __float2half_rn(tile[tx][ty + j * 8]);
        return;
    }
    int i = (bid - PREP_T) * 256 + t;
    if (i >= CVT_CNT) return;
    const float4* s = (const float4*)ehw + i * 2;
    float4 v0 = s[0], v1 = s[1];
    __half2 h[4];
    h[0] = __floats2half2_rn(v0.x, v0.y);
    h[1] = __floats2half2_rn(v0.z, v0.w);
    h[2] = __floats2half2_rn(v1.x, v1.y);
    h[3] = __floats2half2_rn(v1.z, v1.w);
    *(uint4*)(g_ehw + (size_t)i * 8) = *(uint4*)h;
}

// ================= fused layernorm + gating (one block per token) =================
__global__ void ln_gating_kernel(const float* __restrict__ x,
                                 const float* __restrict__ w,
                                 const float* __restrict__ b,
                                 const float* __restrict__ wg) {
    int n = blockIdx.x;
    const float* row = x + (size_t)n * D_DIM;
    __shared__ float rowbuf[D_DIM];
    __shared__ float sh1[8], sh2[8], sl[E_NUM];

    float xv[4];
    float s = 0.f, s2 = 0.f;
    #pragma unroll
    for (int i = 0; i < 4; i++) {
        xv[i] = row[threadIdx.x + i * 256];
        s += xv[i]; s2 += xv[i] * xv[i];
    }
    s = warpRed(s); s2 = warpRed(s2);
    int wi = threadIdx.x >> 5, lane = threadIdx.x & 31;
    if (lane == 0) { sh1[wi] = s; sh2[wi] = s2; }
    __syncthreads();
    if (wi == 0) {
        float a = lane < 8 ? sh1[lane] : 0.f;
        float c = lane < 8 ? sh2[lane] : 0.f;
        a = warpRed(a); c = warpRed(c);
        if (lane == 0) { sh1[0] = a; sh2[0] = c; }
    }
    __syncthreads();
    float mu  = sh1[0] * (1.f / D_DIM);
    float var = sh2[0] * (1.f / D_DIM) - mu * mu;
    float inv = rsqrtf(var + LN_EPS);
    __half* outh = g_xnh + (size_t)n * D_DIM;
    __half* outr = g_xr + (size_t)n * D_DIM;
    #pragma unroll
    for (int i = 0; i < 4; i++) {
        int d = threadIdx.x + i * 256;
        float nv = (xv[i] - mu) * inv * w[d] + b[d];
        rowbuf[d] = nv;
        outh[d] = __float2half_rn(nv);
        outr[d] = __float2half_rn(xv[i]);
    }
    __syncthreads();
    float dot = 0.f;
    for (int d = lane; d < D_DIM; d += 32)
        dot += rowbuf[d] * wg[d * E_NUM + wi];
    dot = warpRed(dot);
    if (lane == 0) sl[wi] = dot;
    __syncthreads();
    if (threadIdx.x == 0) {
        float lg[E_NUM];
        float nrm = 0.f;
        #pragma unroll
        for (int e = 0; e < E_NUM; e++) { lg[e] = sl[e]; nrm += lg[e] * lg[e]; }
        nrm = fmaxf(sqrtf(nrm), 1e-12f);
        float invn = 1.f / nrm;
        #pragma unroll
        for (int e = 0; e < E_NUM; e++) lg[e] *= invn;
        float mx = lg[0];
        #pragma unroll
        for (int e = 1; e < E_NUM; e++) mx = fmaxf(mx, lg[e]);
        float p[E_NUM], ssum = 0.f;
        #pragma unroll
        for (int e = 0; e < E_NUM; e++) { p[e] = expf(lg[e] - mx); ssum += p[e]; }
        float sinv = 1.f / ssum;
        #pragma unroll
        for (int e = 0; e < E_NUM; e++) p[e] *= sinv;
        int i0 = 0;
        #pragma unroll
        for (int e = 1; e < E_NUM; e++) if (lg[e] > lg[i0]) i0 = e;
        int i1 = (i0 == 0) ? 1 : 0;
        #pragma unroll
        for (int e = 0; e < E_NUM; e++) if (e != i0 && lg[e] > lg[i1]) i1 = e;
        g_topidx[n * 2 + 0] = i0; g_gates[n * 2 + 0] = p[i0];
        g_topidx[n * 2 + 1] = i1; g_gates[n * 2 + 1] = p[i1];
        atomicAdd(&g_importance[i0], p[i0]);
        atomicAdd(&g_importance[i1], p[i1]);
        atomicAdd(&g_load[i0], 1);
        atomicAdd(&g_load[i1], 1);
    }
}

// ================= scan + loss + scatter (ONE single-block launch) =================
__global__ void scan_scatter_kernel(float* __restrict__ out) {
    __shared__ int scur[E_NUM];
    __shared__ int soff[E_NUM];
    if (threadIdx.x == 0) {
        int off = 0;
        for (int e = 0; e < E_NUM; e++) { g_offsets[e] = off; soff[e] = off; scur[e] = 0; off += g_load[e]; }
        g_offsets[E_NUM] = off;
        float m = 0.f;
        for (int e = 0; e < E_NUM; e++) m += g_importance[e];
        m *= (1.f / E_NUM);
        float v = 0.f;
        for (int e = 0; e < E_NUM; e++) { float d = g_importance[e] - m; v += d * d; }
        v *= (1.f / (E_NUM - 1));
        float cv1 = v / (m * m + 1e-6f);
        float m2 = 0.f;
        for (int e = 0; e < E_NUM; e++) m2 += (float)g_load[e];
        m2 *= (1.f / E_NUM);
        float v2 = 0.f;
        for (int e = 0; e < E_NUM; e++) { float d = (float)g_load[e] - m2; v2 += d * d; }
        v2 *= (1.f / (E_NUM - 1));
        float cv2 = v2 / (m2 * m2 + 1e-6f);
        size_t base = (size_t)N_TOK * O_DIM;
        out[base] = (cv1 + cv2) * LOSS_COEF;
        float tot = (float)off;
        for (int e = 0; e < E_NUM; e++)
            out[base + 1 + e] = (float)g_load[e] / tot;
    }
    __syncthreads();
    for (int n = threadIdx.x; n < N_TOK; n += blockDim.x) {
        #pragma unroll
        for (int k = 0; k < TOPK; k++) {
            int e = g_topidx[n * 2 + k];
            int slot = atomicAdd(&scur[e], 1);
            int row = soff[e] + slot;
            g_rowtok[row]  = n;
            g_rowgate[row] = g_gates[n * 2 + k];
        }
    }
}

// ================= phase-1: gemm1 (z<8) + proj (z==8) + cvt(ew) overlap (z==9) =================
__global__ __launch_bounds__(NTHR)
void gemm_p1(const float* __restrict__ bias, const float* __restrict__ ew,
             float* __restrict__ y) {
    const int z = blockIdx.z;
    if (z == 9) {
        // overlapped fp32->fp16 conversion of expert output weights (memory-bound;
        // hides under the compute-bound GEMM CTAs). 16*32=512 blocks, grid-stride.
        int nb = gridDim.x * gridDim.y;                  // 512
        int bid = blockIdx.y * gridDim.x + blockIdx.x;
        for (int i = bid * NTHR + threadIdx.x; i < CVT_CNT; i += nb * NTHR) {
            const float4* s = (const float4*)ew + i * 2;
            float4 v0 = s[0], v1 = s[1];
            __half2 h[4];
            h[0] = __floats2half2_rn(v0.x, v0.y);
            h[1] = __floats2half2_rn(v0.z, v0.w);
            h[2] = __floats2half2_rn(v1.x, v1.y);
            h[3] = __floats2half2_rn(v1.z, v1.w);
            *(uint4*)(g_ew + (size_t)i * 8) = *(uint4*)h;
        }
        return;
    }
    const bool isProj = (z == 8);
    int e = isProj ? 0 : z;
    int cntLocal, r0;
    if (isProj) {
        if (blockIdx.x >= O_DIM / CTA_N) return;
        r0 = blockIdx.y * CTA_M;
        cntLocal = CTA_M;
    } else {
        int cnt = g_load[e];
        int byr = blockIdx.y * CTA_M;
        if (byr >= cnt) return;
        cntLocal = cnt - byr; if (cntLocal > CTA_M) cntLocal = CTA_M;
        r0 = g_offsets[e] + byr;
    }
    int n0 = blockIdx.x * CTA_N;
    const __half* B = isProj ? (g_owT + (size_t)n0 * D_DIM)
                             : (g_ehw + (size_t)e * H_DIM * D_DIM + (size_t)n0 * D_DIM);

    __shared__ __align__(16) char smem[2 * STAGE_B];
    uint32_t sbase = smem_u32(smem);

    int t = threadIdx.x, lane = t & 31, wid = t >> 5;
    int m0w = (wid & 1) * 64, n0w = (wid >> 1) * 64;

    const __half* srow[8];
    uint32_t doff[8];
    #pragma unroll
    for (int i = 0; i < 8; i++) {
        int id = t + i * NTHR;
        int c = id & 3, row = id >> 2;
        if (row < CTA_M) {
            int rr = (row < cntLocal) ? row : (cntLocal - 1);
            srow[i] = isProj ? (g_xr + (size_t)(r0 + rr) * D_DIM + c * 8)
                             : (g_xnh + (size_t)g_rowtok[r0 + rr] * D_DIM + c * 8);
        } else {
            srow[i] = B + (size_t)(row - CTA_M) * D_DIM + c * 8;
        }
        doff[i] = (uint32_t)row * ROWB + c * 16;
    }

    auto stage = [&](int s) {
        uint32_t stb = sbase + (uint32_t)(s & 1) * STAGE_B;
        int k0 = s * KS;
        #pragma unroll
        for (int i = 0; i < 8; i++)
            cpasync16(stb + doff[i], srow[i] + k0);
        CP_COMMIT();
    };

    float C[4][8][4] = {};
    const int SLABS = D_DIM / KS;   // 32

    int l7 = lane & 7, lg8 = (lane >> 3) & 1, lg16 = lane >> 4;
    stage(0);
    for (int s = 0; s < SLABS; s++) {
        CP_WAIT(0);
        __syncthreads();
        if (s + 1 < SLABS) stage(s + 1);
        uint32_t Ab = sbase + (uint32_t)(s & 1) * STAGE_B;
        uint32_t Bb = Ab + CTA_M * ROWB;
        // bulk fragment prefetch: ALL 16 LDSM for both kk halves, then 128 MMAs
        uint32_t a[2][4][4], b[2][8][2];
        #pragma unroll
        for (int kk = 0; kk < 2; kk++) {
            #pragma unroll
            for (int mi = 0; mi < 4; mi++)
                ldsm4(a[kk][mi], Ab + (uint32_t)(m0w + mi * 16 + lg8 * 8 + l7) * ROWB
                                    + (uint32_t)(kk * 2 + lg16) * 16);
            #pragma unroll
            for (int p = 0; p < 4; p++) {
                uint32_t r[4];
                ldsm4(r, Bb + (uint32_t)(n0w + p * 16 + lg16 * 8 + l7) * ROWB
                            + (uint32_t)(kk * 2 + lg8) * 16);
                b[kk][2 * p][0] = r[0]; b[kk][2 * p][1] = r[1];
                b[kk][2 * p + 1][0] = r[2]; b[kk][2 * p + 1][1] = r[3];
            }
        }
        #pragma unroll
        for (int kk = 0; kk < 2; kk++)
            #pragma unroll
            for (int mi = 0; mi < 4; mi++)
                #pragma unroll
                for (int nb = 0; nb < 8; nb++)
                    mma16(C[mi][nb], a[kk][mi], b[kk][nb]);
    }

    int g = lane >> 2, tg = lane & 3;
    #pragma unroll
    for (int mi = 0; mi < 4; mi++) {
        int rl0 = m0w + mi * 16 + g;
        int rl1 = rl0 + 8;
        #pragma unroll
        for (int nb = 0; nb < 8; nb++) {
            int col = n0 + n0w + nb * 8 + tg * 2;
            if (isProj) {
                *(float2*)&y[(size_t)(r0 + rl0) * O_DIM + col] = make_float2(C[mi][nb][0], C[mi][nb][1]);
                *(float2*)&y[(size_t)(r0 + rl1) * O_DIM + col] = make_float2(C[mi][nb][2], C[mi][nb][3]);
            } else {
                float b0 = bias[(size_t)e * H_DIM + col], b1 = bias[(size_t)e * H_DIM + col + 1];
                if (rl0 < cntLocal) {
                    float v0 = C[mi][nb][0] + b0; v0 = v0 / (1.f + expf(-v0));
                    float v1 = C[mi][nb][1] + b1; v1 = v1 / (1.f + expf(-v1));
                    *(__half2*)&g_h[(size_t)(r0 + rl0) * H_DIM + col] = __floats2half2_rn(v0, v1);
                }
                if (rl1 < cntLocal) {
                    float v2 = C[mi][nb][2] + b0; v2 = v2 / (1.f + expf(-v2));
                    float v3 = C[mi][nb][3] + b1; v3 = v3 / (1.f + expf(-v3));
                    *(__half2*)&g_h[(size_t)(r0 + rl1) * H_DIM + col] = __floats2half2_rn(v2, v3);
                }
            }
        }
    }
}

// ================= gemm2 (no K-split): y[tok] += gate*(h @ W[e]^T + b) =================
__global__ __launch_bounds__(NTHR)
void gemm_2(const float* __restrict__ bias, float* __restrict__ y) {
    int e = blockIdx.z;
    int cnt = g_load[e];
    int byr = blockIdx.y * CTA_M;
    if (byr >= cnt) return;
    int cntLocal = cnt - byr; if (cntLocal > CTA_M) cntLocal = CTA_M;
    int r0 = g_offsets[e] + byr;
    int n0 = blockIdx.x * CTA_N;
    const __half* B = g_ew + (size_t)e * O_DIM * H_DIM + (size_t)n0 * H_DIM;

    __shared__ __align__(16) char smem[2 * STAGE_B];
    uint32_t sbase = smem_u32(smem);

    int t = threadIdx.x, lane = t & 31, wid = t >> 5;
    int m0w = (wid & 1) * 64, n0w = (wid >> 1) * 64;

    const __half* srow[8];
    uint32_t doff[8];
    #pragma unroll
    for (int i = 0; i < 8; i++) {
        int id = t + i * NTHR;
        int c = id & 3, row = id >> 2;
        if (row < CTA_M) {
            int rr = (row < cntLocal) ? row : (cntLocal - 1);
            srow[i] = g_h + (size_t)(r0 + rr) * H_DIM + c * 8;
        } else {
            srow[i] = B + (size_t)(row - CTA_M) * H_DIM + c * 8;
        }
        doff[i] = (uint32_t)row * ROWB + c * 16;
    }

    auto stage = [&](int s) {
        uint32_t stb = sbase + (uint32_t)(s & 1) * STAGE_B;
        int k0 = s * KS;
        #pragma unroll
        for (int i = 0; i < 8; i++)
            cpasync16(stb + doff[i], srow[i] + k0);
        CP_COMMIT();
    };

    float C[4][8][4] = {};
    const int SLABS = H_DIM / KS;    // 64

    int l7 = lane & 7, lg8 = (lane >> 3) & 1, lg16 = lane >> 4;
    stage(0);
    for (int s = 0; s < SLABS; s++) {
        CP_WAIT(0);
        __syncthreads();
        if (s + 1 < SLABS) stage(s + 1);
        uint32_t Ab = sbase + (uint32_t)(s & 1) * STAGE_B;
        uint32_t Bb = Ab + CTA_M * ROWB;
        uint32_t a[2][4][4], b[2][8][2];
        #pragma unroll
        for (int kk = 0; kk < 2; kk++) {
            #pragma unroll
            for (int mi = 0; mi < 4; mi++)
                ldsm4(a[kk][mi], Ab + (uint32_t)(m0w + mi * 16 + lg8 * 8 + l7) * ROWB
                                    + (uint32_t)(kk * 2 + lg16) * 16);
            #pragma unroll
            for (int p = 0; p < 4; p++) {
                uint32_t r[4];
                ldsm4(r, Bb + (uint32_t)(n0w + p * 16 + lg16 * 8 + l7) * ROWB
                            + (uint32_t)(kk * 2 + lg8) * 16);
                b[kk][2 * p][0] = r[0]; b[kk][2 * p][1] = r[1];
                b[kk][2 * p + 1][0] = r[2]; b[kk][2 * p + 1][1] = r[3];
            }
        }
        #pragma unroll
        for (int kk = 0; kk < 2; kk++)
            #pragma unroll
            for (int mi = 0; mi < 4; mi++)
                #pragma unroll
                for (int nb = 0; nb < 8; nb++)
                    mma16(C[mi][nb], a[kk][mi], b[kk][nb]);
    }

    int g = lane >> 2, tg = lane & 3;
    #pragma unroll
    for (int mi = 0; mi < 4; mi++) {
        int rl0 = m0w + mi * 16 + g;
        int rl1 = rl0 + 8;
        #pragma unroll
        for (int nb = 0; nb < 8; nb++) {
            int col = n0 + n0w + nb * 8 + tg * 2;
            float b0 = bias[(size_t)e * O_DIM + col];
            float b1 = bias[(size_t)e * O_DIM + col + 1];
            if (rl0 < cntLocal) {
                int dr = r0 + rl0;
                int tok = g_rowtok[dr]; float gt = g_rowgate[dr];
                atomicAdd(&y[(size_t)tok * O_DIM + col],     (C[mi][nb][0] + b0) * gt);
                atomicAdd(&y[(size_t)tok * O_DIM + col + 1], (C[mi][nb][1] + b1) * gt);
            }
            if (rl1 < cntLocal) {
                int dr = r0 + rl1;
                int tok = g_rowtok[dr]; float gt = g_rowgate[dr];
                atomicAdd(&y[(size_t)tok * O_DIM + col],     (C[mi][nb][2] + b0) * gt);
                atomicAdd(&y[(size_t)tok * O_DIM + col + 1], (C[mi][nb][3] + b1) * gt);
            }
        }
    }
}

// ---------------- launch ----------------
extern "C" void kernel_launch(void* const* d_in, const int* in_sizes, int n_in,
                              void* d_out, int out_size) {
    const float* x   = (const float*)d_in[0];
    const float* nw  = (const float*)d_in[6];
    const float* nb  = (const float*)d_in[7];
    const float* wg  = (const float*)d_in[9];
    const float* ehw = (const float*)d_in[10];
    const float* ehb = (const float*)d_in[11];
    const float* ew  = (const float*)d_in[12];
    const float* eb  = (const float*)d_in[13];
    const float* ow  = (const float*)d_in[14];
    float* y = (float*)d_out;

    prep_kernel<<<PREP_T + CVT_CNT / 256, 256>>>(ow, ehw);                           // 0
    ln_gating_kernel<<<N_TOK, 256>>>(x, nw, nb, wg);                                 // 1
    scan_scatter_kernel<<<1, 256>>>(y);                                              // 2
    gemm_p1<<<dim3(H_DIM / CTA_N, N_TOK / CTA_M, 10), NTHR>>>(ehb, ew, y);           // 3 <- profiled
    gemm_2<<<dim3(O_DIM / CTA_N, N_TOK / CTA_M, E_NUM), NTHR>>>(eb, y);              // 4
}

// round 17
// speedup vs baseline: 1.0301x; 1.0301x over previous
#include <cuda_runtime.h>
#include <cuda_fp16.h>
#include <math.h>
#include <stdint.h>

// Problem constants
#define N_TOK 4096
#define D_DIM 1024
#define E_NUM 8
#define H_DIM 2048
#define O_DIM 1024
#define TOPK  2
#define NK    (N_TOK*TOPK)
#define LN_EPS 1e-5f
#define LOSS_COEF 0.01f

// GEMM tiling: 128x128 CTA tile, 4 warps (64x64 warp tile), K slab = 32 halves
#define CTA_M 128
#define CTA_N 128
#define KS    32
#define ROWB  80                        // 64B data + 16B pad (conflict-free LDSM)
#define STAGE_B (256 * ROWB)            // A rows 0..127, B rows 128..255 (20480 B)
#define NTHR  128

// ---------------- scratch (allocation-free; device-side access ONLY) ----------------
__device__ __half g_xnh[(size_t)N_TOK * D_DIM];   // LN output fp16 (gemm1 A via rowtok)
__device__ __half g_xr [(size_t)N_TOK * D_DIM];   // half(x): proj A
__device__ __half g_h  [(size_t)NK   * H_DIM];
__device__ __half g_ehw[(size_t)E_NUM * H_DIM * D_DIM];
__device__ __half g_ew [(size_t)E_NUM * O_DIM * H_DIM];
__device__ __half g_owT[(size_t)O_DIM * D_DIM];
__device__ float g_gates[NK];
__device__ int   g_topidx[NK];
__device__ float g_importance[E_NUM];
__device__ int   g_load[E_NUM];
__device__ int   g_offsets[E_NUM + 1];
__device__ int   g_rowtok[NK];
__device__ float g_rowgate[NK];

// ---------------- helpers ----------------
__device__ __forceinline__ uint32_t smem_u32(const void* p) {
    uint32_t a;
    asm("{ .reg .u64 t; cvta.to.shared.u64 t, %1; cvt.u32.u64 %0, t; }" : "=r"(a) : "l"(p));
    return a;
}
__device__ __forceinline__ void cpasync16(uint32_t dst, const void* src) {
    asm volatile("cp.async.cg.shared.global [%0], [%1], 16;\n" :: "r"(dst), "l"(src));
}
#define CP_COMMIT() asm volatile("cp.async.commit_group;\n")
#define CP_WAIT(N)  asm volatile("cp.async.wait_group %0;\n" :: "n"(N))

__device__ __forceinline__ void ldsm4(uint32_t* r, uint32_t addr) {
    asm volatile("ldmatrix.sync.aligned.m8n8.x4.shared.b16 {%0,%1,%2,%3}, [%4];"
        : "=r"(r[0]), "=r"(r[1]), "=r"(r[2]), "=r"(r[3]) : "r"(addr));
}
__device__ __forceinline__ void mma16(float* c, const uint32_t* a, const uint32_t* b) {
    asm volatile("mma.sync.aligned.m16n8k16.row.col.f32.f16.f16.f32 "
        "{%0,%1,%2,%3}, {%4,%5,%6,%7}, {%8,%9}, {%0,%1,%2,%3};"
        : "+f"(c[0]), "+f"(c[1]), "+f"(c[2]), "+f"(c[3])
        : "r"(a[0]), "r"(a[1]), "r"(a[2]), "r"(a[3]), "r"(b[0]), "r"(b[1]));
}
__inline__ __device__ float warpRed(float v) {
    #pragma unroll
    for (int o = 16; o; o >>= 1) v += __shfl_xor_sync(0xffffffffu, v, o);
    return v;
}

// ================= mega front-end: ln_gating + init + transpose_ow + cvt(ehw) + cvt(ew) ====
// block ranges (all 256 threads):
//   [0, 4096)                 : ln_gating, one block per token
//   [4096, 5120)              : transpose_ow (1024 tiles)
//   [5120, 5120+8192)         : cvt ehw
//   [5120+8192, 5120+16384)   : cvt ew
#define MB_LN   N_TOK
#define MB_T    1024
#define MB_CVT  8192
#define CVT_CNT (E_NUM * H_DIM * D_DIM / 8)
__global__ void front_kernel(const float* __restrict__ x,
                             const float* __restrict__ w,
                             const float* __restrict__ b,
                             const float* __restrict__ wg,
                             const float* __restrict__ ow,
                             const float* __restrict__ ehw,
                             const float* __restrict__ ew) {
    int bid = blockIdx.x;
    int t = threadIdx.x;
    if (bid < MB_LN) {
        int n = bid;
        if (n == 0 && t < E_NUM) { g_importance[t] = 0.f; g_load[t] = 0; }
        const float* row = x + (size_t)n * D_DIM;
        __shared__ float rowbuf[D_DIM];
        __shared__ float sh1[8], sh2[8], sl[E_NUM];
        float xv[4];
        float s = 0.f, s2 = 0.f;
        #pragma unroll
        for (int i = 0; i < 4; i++) {
            xv[i] = row[t + i * 256];
            s += xv[i]; s2 += xv[i] * xv[i];
        }
        s = warpRed(s); s2 = warpRed(s2);
        int wi = t >> 5, lane = t & 31;
        if (lane == 0) { sh1[wi] = s; sh2[wi] = s2; }
        __syncthreads();
        if (wi == 0) {
            float a = lane < 8 ? sh1[lane] : 0.f;
            float c = lane < 8 ? sh2[lane] : 0.f;
            a = warpRed(a); c = warpRed(c);
            if (lane == 0) { sh1[0] = a; sh2[0] = c; }
        }
        __syncthreads();
        float mu  = sh1[0] * (1.f / D_DIM);
        float var = sh2[0] * (1.f / D_DIM) - mu * mu;
        float inv = rsqrtf(var + LN_EPS);
        __half* outh = g_xnh + (size_t)n * D_DIM;
        __half* outr = g_xr + (size_t)n * D_DIM;
        #pragma unroll
        for (int i = 0; i < 4; i++) {
            int d = t + i * 256;
            float nv = (xv[i] - mu) * inv * w[d] + b[d];
            rowbuf[d] = nv;
            outh[d] = __float2half_rn(nv);
            outr[d] = __float2half_rn(xv[i]);
        }
        __syncthreads();
        float dot = 0.f;
        for (int d = lane; d < D_DIM; d += 32)
            dot += rowbuf[d] * wg[d * E_NUM + wi];
        dot = warpRed(dot);
        if (lane == 0) sl[wi] = dot;
        __syncthreads();
        if (t == 0) {
            float lg[E_NUM];
            float nrm = 0.f;
            #pragma unroll
            for (int e = 0; e < E_NUM; e++) { lg[e] = sl[e]; nrm += lg[e] * lg[e]; }
            nrm = fmaxf(sqrtf(nrm), 1e-12f);
            float invn = 1.f / nrm;
            #pragma unroll
            for (int e = 0; e < E_NUM; e++) lg[e] *= invn;
            float mx = lg[0];
            #pragma unroll
            for (int e = 1; e < E_NUM; e++) mx = fmaxf(mx, lg[e]);
            float p[E_NUM], ssum = 0.f;
            #pragma unroll
            for (int e = 0; e < E_NUM; e++) { p[e] = expf(lg[e] - mx); ssum += p[e]; }
            float sinv = 1.f / ssum;
            #pragma unroll
            for (int e = 0; e < E_NUM; e++) p[e] *= sinv;
            int i0 = 0;
            #pragma unroll
            for (int e = 1; e < E_NUM; e++) if (lg[e] > lg[i0]) i0 = e;
            int i1 = (i0 == 0) ? 1 : 0;
            #pragma unroll
            for (int e = 0; e < E_NUM; e++) if (e != i0 && lg[e] > lg[i1]) i1 = e;
            g_topidx[n * 2 + 0] = i0; g_gates[n * 2 + 0] = p[i0];
            g_topidx[n * 2 + 1] = i1; g_gates[n * 2 + 1] = p[i1];
            atomicAdd(&g_importance[i0], p[i0]);
            atomicAdd(&g_importance[i1], p[i1]);
            atomicAdd(&g_load[i0], 1);
            atomicAdd(&g_load[i1], 1);
        }
        return;
    }
    if (bid < MB_LN + MB_T) {
        int tb = bid - MB_LN;
        __shared__ float tile[32][33];
        int ox = tb & 31, dy = tb >> 5;
        int tx = t & 31, ty = t >> 5;
        int o = ox * 32 + tx;
        int d0 = dy * 32;
        #pragma unroll
        for (int j = 0; j < 4; j++)
            tile[ty + j * 8][tx] = ow[(size_t)(d0 + ty + j * 8) * O_DIM + o];
        __syncthreads();
        int d = d0 + tx;
        int o2 = ox * 32;
        #pragma unroll
        for (int j = 0; j < 4; j++)
            g_owT[(size_t)(o2 + ty + j * 8) * D_DIM + d] =
                __float2half_rn(tile[tx][ty + j * 8]);
        return;
    }
    const float* src;
    __half* dst;
    int i;
    if (bid < MB_LN + MB_T + MB_CVT) {
        i = (bid - MB_LN - MB_T) * 256 + t; src = ehw; dst = g_ehw;
    } else {
        i = (bid - MB_LN - MB_T - MB_CVT) * 256 + t; src = ew; dst = g_ew;
    }
    if (i >= CVT_CNT) return;
    const float4* s = (const float4*)src + i * 2;
    float4 v0 = s[0], v1 = s[1];
    __half2 h[4];
    h[0] = __floats2half2_rn(v0.x, v0.y);
    h[1] = __floats2half2_rn(v0.z, v0.w);
    h[2] = __floats2half2_rn(v1.x, v1.y);
    h[3] = __floats2half2_rn(v1.z, v1.w);
    *(uint4*)(dst + (size_t)i * 8) = *(uint4*)h;
}

// ================= scan + loss + scatter (ONE single-block launch) =================
__global__ void scan_scatter_kernel(float* __restrict__ out) {
    __shared__ int scur[E_NUM];
    __shared__ int soff[E_NUM];
    if (threadIdx.x == 0) {
        int off = 0;
        for (int e = 0; e < E_NUM; e++) { g_offsets[e] = off; soff[e] = off; scur[e] = 0; off += g_load[e]; }
        g_offsets[E_NUM] = off;
        float m = 0.f;
        for (int e = 0; e < E_NUM; e++) m += g_importance[e];
        m *= (1.f / E_NUM);
        float v = 0.f;
        for (int e = 0; e < E_NUM; e++) { float d = g_importance[e] - m; v += d * d; }
        v *= (1.f / (E_NUM - 1));
        float cv1 = v / (m * m + 1e-6f);
        float m2 = 0.f;
        for (int e = 0; e < E_NUM; e++) m2 += (float)g_load[e];
        m2 *= (1.f / E_NUM);
        float v2 = 0.f;
        for (int e = 0; e < E_NUM; e++) { float d = (float)g_load[e] - m2; v2 += d * d; }
        v2 *= (1.f / (E_NUM - 1));
        float cv2 = v2 / (m2 * m2 + 1e-6f);
        size_t base = (size_t)N_TOK * O_DIM;
        out[base] = (cv1 + cv2) * LOSS_COEF;
        float tot = (float)off;
        for (int e = 0; e < E_NUM; e++)
            out[base + 1 + e] = (float)g_load[e] / tot;
    }
    __syncthreads();
    for (int n = threadIdx.x; n < N_TOK; n += blockDim.x) {
        #pragma unroll
        for (int k = 0; k < TOPK; k++) {
            int e = g_topidx[n * 2 + k];
            int slot = atomicAdd(&scur[e], 1);
            int row = soff[e] + slot;
            g_rowtok[row]  = n;
            g_rowgate[row] = g_gates[n * 2 + k];
        }
    }
}

// ================= phase-1 GEMM: gemm1 (z<8) + proj (z==8) =================
__global__ __launch_bounds__(NTHR)
void gemm_p1(const float* __restrict__ bias, float* __restrict__ y) {
    const int z = blockIdx.z;
    const bool isProj = (z == 8);
    int e = isProj ? 0 : z;
    int cntLocal, r0;
    if (isProj) {
        if (blockIdx.x >= O_DIM / CTA_N) return;
        r0 = blockIdx.y * CTA_M;
        cntLocal = CTA_M;
    } else {
        int cnt = g_load[e];
        int byr = blockIdx.y * CTA_M;
        if (byr >= cnt) return;
        cntLocal = cnt - byr; if (cntLocal > CTA_M) cntLocal = CTA_M;
        r0 = g_offsets[e] + byr;
    }
    int n0 = blockIdx.x * CTA_N;
    const __half* B = isProj ? (g_owT + (size_t)n0 * D_DIM)
                             : (g_ehw + (size_t)e * H_DIM * D_DIM + (size_t)n0 * D_DIM);

    __shared__ __align__(16) char smem[2 * STAGE_B];
    uint32_t sbase = smem_u32(smem);

    int t = threadIdx.x, lane = t & 31, wid = t >> 5;
    int m0w = (wid & 1) * 64, n0w = (wid >> 1) * 64;

    const __half* srow[8];
    uint32_t doff[8];
    #pragma unroll
    for (int i = 0; i < 8; i++) {
        int id = t + i * NTHR;
        int c = id & 3, row = id >> 2;
        if (row < CTA_M) {
            int rr = (row < cntLocal) ? row : (cntLocal - 1);
            srow[i] = isProj ? (g_xr + (size_t)(r0 + rr) * D_DIM + c * 8)
                             : (g_xnh + (size_t)g_rowtok[r0 + rr] * D_DIM + c * 8);
        } else {
            srow[i] = B + (size_t)(row - CTA_M) * D_DIM + c * 8;
        }
        doff[i] = (uint32_t)row * ROWB + c * 16;
    }

    auto stage = [&](int s) {
        uint32_t stb = sbase + (uint32_t)(s & 1) * STAGE_B;
        int k0 = s * KS;
        #pragma unroll
        for (int i = 0; i < 8; i++)
            cpasync16(stb + doff[i], srow[i] + k0);
        CP_COMMIT();
    };

    float C[4][8][4] = {};
    const int SLABS = D_DIM / KS;   // 32
    int l7 = lane & 7, lg8 = (lane >> 3) & 1, lg16 = lane >> 4;

    stage(0);
    for (int s = 0; s < SLABS; s++) {
        CP_WAIT(0);
        __syncthreads();
        if (s + 1 < SLABS) stage(s + 1);
        uint32_t Ab = sbase + (uint32_t)(s & 1) * STAGE_B;
        uint32_t Bb = Ab + CTA_M * ROWB;
        #pragma unroll
        for (int kk = 0; kk < 2; kk++) {
            uint32_t a[4][4], b[8][2];
            #pragma unroll
            for (int mi = 0; mi < 4; mi++)
                ldsm4(a[mi], Ab + (uint32_t)(m0w + mi * 16 + lg8 * 8 + l7) * ROWB
                                + (uint32_t)(kk * 2 + lg16) * 16);
            #pragma unroll
            for (int p = 0; p < 4; p++) {
                uint32_t r[4];
                ldsm4(r, Bb + (uint32_t)(n0w + p * 16 + lg16 * 8 + l7) * ROWB
                            + (uint32_t)(kk * 2 + lg8) * 16);
                b[2 * p][0] = r[0]; b[2 * p][1] = r[1];
                b[2 * p + 1][0] = r[2]; b[2 * p + 1][1] = r[3];
            }
            #pragma unroll
            for (int mi = 0; mi < 4; mi++)
                #pragma unroll
                for (int nb = 0; nb < 8; nb++)
                    mma16(C[mi][nb], a[mi], b[nb]);
        }
    }

    int g = lane >> 2, tg = lane & 3;
    #pragma unroll
    for (int mi = 0; mi < 4; mi++) {
        int rl0 = m0w + mi * 16 + g;
        int rl1 = rl0 + 8;
        #pragma unroll
        for (int nb = 0; nb < 8; nb++) {
            int col = n0 + n0w + nb * 8 + tg * 2;
            if (isProj) {
                *(float2*)&y[(size_t)(r0 + rl0) * O_DIM + col] = make_float2(C[mi][nb][0], C[mi][nb][1]);
                *(float2*)&y[(size_t)(r0 + rl1) * O_DIM + col] = make_float2(C[mi][nb][2], C[mi][nb][3]);
            } else {
                float b0 = bias[(size_t)e * H_DIM + col], b1 = bias[(size_t)e * H_DIM + col + 1];
                if (rl0 < cntLocal) {
                    float v0 = C[mi][nb][0] + b0; v0 = v0 / (1.f + expf(-v0));
                    float v1 = C[mi][nb][1] + b1; v1 = v1 / (1.f + expf(-v1));
                    *(__half2*)&g_h[(size_t)(r0 + rl0) * H_DIM + col] = __floats2half2_rn(v0, v1);
                }
                if (rl1 < cntLocal) {
                    float v2 = C[mi][nb][2] + b0; v2 = v2 / (1.f + expf(-v2));
                    float v3 = C[mi][nb][3] + b1; v3 = v3 / (1.f + expf(-v3));
                    *(__half2*)&g_h[(size_t)(r0 + rl1) * H_DIM + col] = __floats2half2_rn(v2, v3);
                }
            }
        }
    }
}

// ================= gemm2: y[tok] += gate*(h @ W[e]^T + b) =================
__global__ __launch_bounds__(NTHR)
void gemm_2(const float* __restrict__ bias, float* __restrict__ y) {
    int e = blockIdx.z;
    int cnt = g_load[e];
    int byr = blockIdx.y * CTA_M;
    if (byr >= cnt) return;
    int cntLocal = cnt - byr; if (cntLocal > CTA_M) cntLocal = CTA_M;
    int r0 = g_offsets[e] + byr;
    int n0 = blockIdx.x * CTA_N;
    const __half* B = g_ew + (size_t)e * O_DIM * H_DIM + (size_t)n0 * H_DIM;

    __shared__ __align__(16) char smem[2 * STAGE_B];
    uint32_t sbase = smem_u32(smem);

    int t = threadIdx.x, lane = t & 31, wid = t >> 5;
    int m0w = (wid & 1) * 64, n0w = (wid >> 1) * 64;

    const __half* srow[8];
    uint32_t doff[8];
    #pragma unroll
    for (int i = 0; i < 8; i++) {
        int id = t + i * NTHR;
        int c = id & 3, row = id >> 2;
        if (row < CTA_M) {
            int rr = (row < cntLocal) ? row : (cntLocal - 1);
            srow[i] = g_h + (size_t)(r0 + rr) * H_DIM + c * 8;
        } else {
            srow[i] = B + (size_t)(row - CTA_M) * H_DIM + c * 8;
        }
        doff[i] = (uint32_t)row * ROWB + c * 16;
    }

    auto stage = [&](int s) {
        uint32_t stb = sbase + (uint32_t)(s & 1) * STAGE_B;
        int k0 = s * KS;
        #pragma unroll
        for (int i = 0; i < 8; i++)
            cpasync16(stb + doff[i], srow[i] + k0);
        CP_COMMIT();
    };

    float C[4][8][4] = {};
    const int SLABS = H_DIM / KS;    // 64
    int l7 = lane & 7, lg8 = (lane >> 3) & 1, lg16 = lane >> 4;

    stage(0);
    for (int s = 0; s < SLABS; s++) {
        CP_WAIT(0);
        __syncthreads();
        if (s + 1 < SLABS) stage(s + 1);
        uint32_t Ab = sbase + (uint32_t)(s & 1) * STAGE_B;
        uint32_t Bb = Ab + CTA_M * ROWB;
        #pragma unroll
        for (int kk = 0; kk < 2; kk++) {
            uint32_t a[4][4], b[8][2];
            #pragma unroll
            for (int mi = 0; mi < 4; mi++)
                ldsm4(a[mi], Ab + (uint32_t)(m0w + mi * 16 + lg8 * 8 + l7) * ROWB
                                + (uint32_t)(kk * 2 + lg16) * 16);
            #pragma unroll
            for (int p = 0; p < 4; p++) {
                uint32_t r[4];
                ldsm4(r, Bb + (uint32_t)(n0w + p * 16 + lg16 * 8 + l7) * ROWB
                            + (uint32_t)(kk * 2 + lg8) * 16);
                b[2 * p][0] = r[0]; b[2 * p][1] = r[1];
                b[2 * p + 1][0] = r[2]; b[2 * p + 1][1] = r[3];
            }
            #pragma unroll
            for (int mi = 0; mi < 4; mi++)
                #pragma unroll
                for (int nb = 0; nb < 8; nb++)
                    mma16(C[mi][nb], a[mi], b[nb]);
        }
    }

    int g = lane >> 2, tg = lane & 3;
    #pragma unroll
    for (int mi = 0; mi < 4; mi++) {
        int rl0 = m0w + mi * 16 + g;
        int rl1 = rl0 + 8;
        #pragma unroll
        for (int nb = 0; nb < 8; nb++) {
            int col = n0 + n0w + nb * 8 + tg * 2;
            float b0 = bias[(size_t)e * O_DIM + col];
            float b1 = bias[(size_t)e * O_DIM + col + 1];
            if (rl0 < cntLocal) {
                int dr = r0 + rl0;
                int tok = g_rowtok[dr]; float gt = g_rowgate[dr];
                atomicAdd(&y[(size_t)tok * O_DIM + col],     (C[mi][nb][0] + b0) * gt);
                atomicAdd(&y[(size_t)tok * O_DIM + col + 1], (C[mi][nb][1] + b1) * gt);
            }
            if (rl1 < cntLocal) {
                int dr = r0 + rl1;
                int tok = g_rowtok[dr]; float gt = g_rowgate[dr];
                atomicAdd(&y[(size_t)tok * O_DIM + col],     (C[mi][nb][2] + b0) * gt);
                atomicAdd(&y[(size_t)tok * O_DIM + col + 1], (C[mi][nb][3] + b1) * gt);
            }
        }
    }
}

// ---------------- launch ----------------
extern "C" void kernel_launch(void* const* d_in, const int* in_sizes, int n_in,
                              void* d_out, int out_size) {
    const float* x   = (const float*)d_in[0];
    const float* nw  = (const float*)d_in[6];
    const float* nb  = (const float*)d_in[7];
    const float* wg  = (const float*)d_in[9];
    const float* ehw = (const float*)d_in[10];
    const float* ehb = (const float*)d_in[11];
    const float* ew  = (const float*)d_in[12];
    const float* eb  = (const float*)d_in[13];
    const float* ow  = (const float*)d_in[14];
    float* y = (float*)d_out;

    front_kernel<<<MB_LN + MB_T + 2 * MB_CVT, 256>>>(x, nw, nb, wg, ow, ehw, ew);    // 0
    scan_scatter_kernel<<<1, 256>>>(y);                                              // 1
    gemm_p1<<<dim3(H_DIM / CTA_N, N_TOK / CTA_M, 9), NTHR>>>(ehb, y);                // 2
    gemm_2<<<dim3(O_DIM / CTA_N, N_TOK / CTA_M, E_NUM), NTHR>>>(eb, y);              // 3 <- profiled
}